// round 4
// baseline (speedup 1.0000x reference)
#include <cuda_runtime.h>

#define ACC 23

struct Consts {
    int   nm_x,  sr_x,  sl_x,  left_x;
    int   nm_id, sr_id, sl_id, left_id;
    float scale;
};
__device__ Consts g_c;

// One-thread prologue: all the fp64 frexp/divide work happens exactly once.
__global__ void setup_kernel(const float* __restrict__ pre_sf,
                             const float* __restrict__ id_sf,
                             const float* __restrict__ x_min,
                             const float* __restrict__ x_max) {
    // symmetric_linear_quantization_params, computed in float32 like the reference
    float scale = fmaxf(fabsf(x_min[0]), fabsf(x_max[0]));
    scale = fmaxf(scale, 1e-8f);
    scale = scale / 127.0f;

    double s64 = (double)scale;
    {
        double ns = (double)pre_sf[0] / s64;
        int e; double m = frexp(ns, &e);             // m in [0.5, 1)
        g_c.nm_x   = (int)llrint(m * 8388608.0);     // round-half-even == jnp.round
        g_c.sl_x   = max(e - ACC, 0);
        g_c.sr_x   = max(ACC - e, 0);
        g_c.left_x = (e - ACC) >= 0;
    }
    {
        double ns = (double)id_sf[0] / s64;
        int e; double m = frexp(ns, &e);
        g_c.nm_id   = (int)llrint(m * 8388608.0);
        g_c.sl_id   = max(e - ACC, 0);
        g_c.sr_id   = max(ACC - e, 0);
        g_c.left_id = (e - ACC) >= 0;
    }
    g_c.scale = scale;
}

// Bit-exact integer multiply-shift-round (round half away from zero)
__device__ __forceinline__ long long fpmul(int xi, int nm, int sr, int sl, int left) {
    long long tmp = (long long)xi * (long long)nm;   // IMAD.WIDE
    if (left) return tmp << sl;
    if (sr == 0) return tmp;
    long long nudge = (1LL << (sr - 1)) - (long long)(tmp < 0);
    return (tmp + nudge) >> sr;                      // arithmetic shift
}

__device__ __forceinline__ float quant_one(float xv, float iv, const Consts& c) {
    int xi = (int)xv;       // exact: inputs are integer-valued fp32
    int ii = (int)iv;
    long long rx = fpmul(xi, c.nm_x,  c.sr_x,  c.sl_x,  c.left_x);
    long long ri = fpmul(ii, c.nm_id, c.sr_id, c.sl_id, c.left_id);
    long long s  = rx + ri;
    int q = (int)(s < -128 ? -128 : (s > 127 ? 127 : s));
    return (float)q * c.scale;
}

__global__ void quant_kernel(const float4* __restrict__ x,
                             const float4* __restrict__ idn,
                             float4* __restrict__ out, int n4) {
    int i = blockIdx.x * blockDim.x + threadIdx.x;
    if (i >= n4) return;
    Consts c = g_c;
    float4 xv = x[i];
    float4 iv = idn[i];
    float4 ov;
    ov.x = quant_one(xv.x, iv.x, c);
    ov.y = quant_one(xv.y, iv.y, c);
    ov.z = quant_one(xv.z, iv.z, c);
    ov.w = quant_one(xv.w, iv.w, c);
    out[i] = ov;
}

// Handle a non-multiple-of-4 remainder (not expected for this shape, but safe)
__global__ void quant_tail_kernel(const float* __restrict__ x,
                                  const float* __restrict__ idn,
                                  float* __restrict__ out, int start, int n) {
    int i = start + blockIdx.x * blockDim.x + threadIdx.x;
    if (i >= n) return;
    Consts c = g_c;
    out[i] = quant_one(x[i], idn[i], c);
}

// Fill any extra output elements (the reference also returns `scale`)
__global__ void scale_tail_kernel(float* __restrict__ out, int n, int out_size) {
    int i = n + blockIdx.x * blockDim.x + threadIdx.x;
    if (i < out_size) out[i] = g_c.scale;
}

extern "C" void kernel_launch(void* const* d_in, const int* in_sizes, int n_in,
                              void* d_out, int out_size) {
    const float* x      = (const float*)d_in[0];
    const float* idn    = (const float*)d_in[1];
    const float* pre_sf = (const float*)d_in[2];
    const float* id_sf  = (const float*)d_in[3];
    const float* x_min  = (const float*)d_in[4];
    const float* x_max  = (const float*)d_in[5];
    float* out = (float*)d_out;

    int n = in_sizes[0];

    setup_kernel<<<1, 1>>>(pre_sf, id_sf, x_min, x_max);

    int n4 = n >> 2;
    if (n4 > 0) {
        int threads = 256;
        int blocks = (n4 + threads - 1) / threads;
        quant_kernel<<<blocks, threads>>>((const float4*)x, (const float4*)idn,
                                          (float4*)out, n4);
    }
    int rem_start = n4 << 2;
    if (rem_start < n) {
        int rem = n - rem_start;
        quant_tail_kernel<<<(rem + 255) / 256, 256>>>(x, idn, out, rem_start, n);
    }
    if (out_size > n) {
        int extra = out_size - n;
        scale_tail_kernel<<<(extra + 255) / 256, 256>>>(out, n, out_size);
    }
}

// round 8
// speedup vs baseline: 1.0030x; 1.0030x over previous
#include <cuda_runtime.h>

#define ACC 23

struct Consts {
    int   nm_x,  sr_x,  sl_x,  left_x;
    int   nm_id, sr_id, sl_id, left_id;
    float scale;
};
__device__ Consts g_c;

// One-thread prologue: all the fp64 frexp/divide work happens exactly once.
__global__ void setup_kernel(const float* __restrict__ pre_sf,
                             const float* __restrict__ id_sf,
                             const float* __restrict__ x_min,
                             const float* __restrict__ x_max) {
    // symmetric_linear_quantization_params, computed in float32 like the reference
    float scale = fmaxf(fabsf(x_min[0]), fabsf(x_max[0]));
    scale = fmaxf(scale, 1e-8f);
    scale = scale / 127.0f;

    double s64 = (double)scale;
    {
        double ns = (double)pre_sf[0] / s64;
        int e; double m = frexp(ns, &e);             // m in [0.5, 1)
        g_c.nm_x   = (int)llrint(m * 8388608.0);     // round-half-even == jnp.round
        g_c.sl_x   = max(e - ACC, 0);
        g_c.sr_x   = max(ACC - e, 0);
        g_c.left_x = (e - ACC) >= 0;
    }
    {
        double ns = (double)id_sf[0] / s64;
        int e; double m = frexp(ns, &e);
        g_c.nm_id   = (int)llrint(m * 8388608.0);
        g_c.sl_id   = max(e - ACC, 0);
        g_c.sr_id   = max(ACC - e, 0);
        g_c.left_id = (e - ACC) >= 0;
    }
    g_c.scale = scale;
}

// Bit-exact integer multiply-shift-round (round half away from zero)
__device__ __forceinline__ long long fpmul(int xi, int nm, int sr, int sl, int left) {
    long long tmp = (long long)xi * (long long)nm;   // IMAD.WIDE
    if (left) return tmp << sl;
    if (sr == 0) return tmp;
    long long nudge = (1LL << (sr - 1)) - (long long)(tmp < 0);
    return (tmp + nudge) >> sr;                      // arithmetic shift
}

__device__ __forceinline__ float quant_one(float xv, float iv, const Consts& c) {
    int xi = (int)xv;       // exact: inputs are integer-valued fp32
    int ii = (int)iv;
    long long rx = fpmul(xi, c.nm_x,  c.sr_x,  c.sl_x,  c.left_x);
    long long ri = fpmul(ii, c.nm_id, c.sr_id, c.sl_id, c.left_id);
    long long s  = rx + ri;
    int q = (int)(s < -128 ? -128 : (s > 127 ? 127 : s));
    return (float)q * c.scale;
}

__global__ void quant_kernel(const float4* __restrict__ x,
                             const float4* __restrict__ idn,
                             float4* __restrict__ out, int n4) {
    int i = blockIdx.x * blockDim.x + threadIdx.x;
    if (i >= n4) return;
    Consts c = g_c;
    float4 xv = x[i];
    float4 iv = idn[i];
    float4 ov;
    ov.x = quant_one(xv.x, iv.x, c);
    ov.y = quant_one(xv.y, iv.y, c);
    ov.z = quant_one(xv.z, iv.z, c);
    ov.w = quant_one(xv.w, iv.w, c);
    out[i] = ov;
}

// Handle a non-multiple-of-4 remainder (not expected for this shape, but safe)
__global__ void quant_tail_kernel(const float* __restrict__ x,
                                  const float* __restrict__ idn,
                                  float* __restrict__ out, int start, int n) {
    int i = start + blockIdx.x * blockDim.x + threadIdx.x;
    if (i >= n) return;
    Consts c = g_c;
    out[i] = quant_one(x[i], idn[i], c);
}

// Fill any extra output elements (the reference also returns `scale`)
__global__ void scale_tail_kernel(float* __restrict__ out, int n, int out_size) {
    int i = n + blockIdx.x * blockDim.x + threadIdx.x;
    if (i < out_size) out[i] = g_c.scale;
}

extern "C" void kernel_launch(void* const* d_in, const int* in_sizes, int n_in,
                              void* d_out, int out_size) {
    const float* x      = (const float*)d_in[0];
    const float* idn    = (const float*)d_in[1];
    const float* pre_sf = (const float*)d_in[2];
    const float* id_sf  = (const float*)d_in[3];
    const float* x_min  = (const float*)d_in[4];
    const float* x_max  = (const float*)d_in[5];
    float* out = (float*)d_out;

    int n = in_sizes[0];

    setup_kernel<<<1, 1>>>(pre_sf, id_sf, x_min, x_max);

    int n4 = n >> 2;
    if (n4 > 0) {
        int threads = 256;
        int blocks = (n4 + threads - 1) / threads;
        quant_kernel<<<blocks, threads>>>((const float4*)x, (const float4*)idn,
                                          (float4*)out, n4);
    }
    int rem_start = n4 << 2;
    if (rem_start < n) {
        int rem = n - rem_start;
        quant_tail_kernel<<<(rem + 255) / 256, 256>>>(x, idn, out, rem_start, n);
    }
    if (out_size > n) {
        int extra = out_size - n;
        scale_tail_kernel<<<(extra + 255) / 256, 256>>>(out, n, out_size);
    }
}

// round 9
// speedup vs baseline: 1.0037x; 1.0007x over previous
#include <cuda_runtime.h>

#define ACC 23

struct Consts {
    int   nm_x,  sr_x,  sl_x,  left_x;
    int   nm_id, sr_id, sl_id, left_id;
    float scale;
};
__device__ Consts g_c;

// One-thread prologue: all the fp64 frexp/divide work happens exactly once.
__global__ void setup_kernel(const float* __restrict__ pre_sf,
                             const float* __restrict__ id_sf,
                             const float* __restrict__ x_min,
                             const float* __restrict__ x_max) {
    // symmetric_linear_quantization_params, computed in float32 like the reference
    float scale = fmaxf(fabsf(x_min[0]), fabsf(x_max[0]));
    scale = fmaxf(scale, 1e-8f);
    scale = scale / 127.0f;

    double s64 = (double)scale;
    {
        double ns = (double)pre_sf[0] / s64;
        int e; double m = frexp(ns, &e);             // m in [0.5, 1)
        g_c.nm_x   = (int)llrint(m * 8388608.0);     // round-half-even == jnp.round
        g_c.sl_x   = max(e - ACC, 0);
        g_c.sr_x   = max(ACC - e, 0);
        g_c.left_x = (e - ACC) >= 0;
    }
    {
        double ns = (double)id_sf[0] / s64;
        int e; double m = frexp(ns, &e);
        g_c.nm_id   = (int)llrint(m * 8388608.0);
        g_c.sl_id   = max(e - ACC, 0);
        g_c.sr_id   = max(ACC - e, 0);
        g_c.left_id = (e - ACC) >= 0;
    }
    g_c.scale = scale;
}

// Bit-exact integer multiply-shift-round (round half away from zero)
__device__ __forceinline__ long long fpmul(int xi, int nm, int sr, int sl, int left) {
    long long tmp = (long long)xi * (long long)nm;   // IMAD.WIDE
    if (left) return tmp << sl;
    if (sr == 0) return tmp;
    long long nudge = (1LL << (sr - 1)) - (long long)(tmp < 0);
    return (tmp + nudge) >> sr;                      // arithmetic shift
}

__device__ __forceinline__ float quant_one(float xv, float iv, const Consts& c) {
    int xi = (int)xv;       // exact: inputs are integer-valued fp32
    int ii = (int)iv;
    long long rx = fpmul(xi, c.nm_x,  c.sr_x,  c.sl_x,  c.left_x);
    long long ri = fpmul(ii, c.nm_id, c.sr_id, c.sl_id, c.left_id);
    long long s  = rx + ri;
    int q = (int)(s < -128 ? -128 : (s > 127 ? 127 : s));
    return (float)q * c.scale;
}

__global__ void quant_kernel(const float4* __restrict__ x,
                             const float4* __restrict__ idn,
                             float4* __restrict__ out, int n4) {
    int i = blockIdx.x * blockDim.x + threadIdx.x;
    if (i >= n4) return;
    Consts c = g_c;
    float4 xv = x[i];
    float4 iv = idn[i];
    float4 ov;
    ov.x = quant_one(xv.x, iv.x, c);
    ov.y = quant_one(xv.y, iv.y, c);
    ov.z = quant_one(xv.z, iv.z, c);
    ov.w = quant_one(xv.w, iv.w, c);
    out[i] = ov;
}

// Handle a non-multiple-of-4 remainder (not expected for this shape, but safe)
__global__ void quant_tail_kernel(const float* __restrict__ x,
                                  const float* __restrict__ idn,
                                  float* __restrict__ out, int start, int n) {
    int i = start + blockIdx.x * blockDim.x + threadIdx.x;
    if (i >= n) return;
    Consts c = g_c;
    out[i] = quant_one(x[i], idn[i], c);
}

// Fill any extra output elements (the reference also returns `scale`)
__global__ void scale_tail_kernel(float* __restrict__ out, int n, int out_size) {
    int i = n + blockIdx.x * blockDim.x + threadIdx.x;
    if (i < out_size) out[i] = g_c.scale;
}

extern "C" void kernel_launch(void* const* d_in, const int* in_sizes, int n_in,
                              void* d_out, int out_size) {
    const float* x      = (const float*)d_in[0];
    const float* idn    = (const float*)d_in[1];
    const float* pre_sf = (const float*)d_in[2];
    const float* id_sf  = (const float*)d_in[3];
    const float* x_min  = (const float*)d_in[4];
    const float* x_max  = (const float*)d_in[5];
    float* out = (float*)d_out;

    int n = in_sizes[0];

    setup_kernel<<<1, 1>>>(pre_sf, id_sf, x_min, x_max);

    int n4 = n >> 2;
    if (n4 > 0) {
        int threads = 256;
        int blocks = (n4 + threads - 1) / threads;
        quant_kernel<<<blocks, threads>>>((const float4*)x, (const float4*)idn,
                                          (float4*)out, n4);
    }
    int rem_start = n4 << 2;
    if (rem_start < n) {
        int rem = n - rem_start;
        quant_tail_kernel<<<(rem + 255) / 256, 256>>>(x, idn, out, rem_start, n);
    }
    if (out_size > n) {
        int extra = out_size - n;
        scale_tail_kernel<<<(extra + 255) / 256, 256>>>(out, n, out_size);
    }
}

// round 10
// speedup vs baseline: 1.2516x; 1.2470x over previous
#include <cuda_runtime.h>

#define ACC 23

struct Consts {
    int       nm_x, nm_id;
    int       sr_x, sr_id;
    int       sl_x, sl_id;
    int       left_x, left_id;
    long long kx, kid;       // (1 << (sr-1)) rounding constants, 0 if sr==0
    float     scale;
};

// Exact replication of the reference's fp64 scale decomposition.
__device__ __forceinline__ void compute_consts(const float* __restrict__ pre_sf,
                                               const float* __restrict__ id_sf,
                                               const float* __restrict__ x_min,
                                               const float* __restrict__ x_max,
                                               Consts* c) {
    float scale = fmaxf(fabsf(x_min[0]), fabsf(x_max[0]));
    scale = fmaxf(scale, 1e-8f);
    scale = scale / 127.0f;
    double s64 = (double)scale;
    {
        double ns = (double)pre_sf[0] / s64;
        int e; double m = frexp(ns, &e);             // m in [0.5, 1)
        c->nm_x   = (int)llrint(m * 8388608.0);      // round-half-even == jnp.round
        c->sl_x   = max(e - ACC, 0);
        c->sr_x   = max(ACC - e, 0);
        c->left_x = (e - ACC) >= 0;
        c->kx     = (c->sr_x > 0) ? (1LL << (c->sr_x - 1)) : 0LL;
    }
    {
        double ns = (double)id_sf[0] / s64;
        int e; double m = frexp(ns, &e);
        c->nm_id   = (int)llrint(m * 8388608.0);
        c->sl_id   = max(e - ACC, 0);
        c->sr_id   = max(ACC - e, 0);
        c->left_id = (e - ACC) >= 0;
        c->kid     = (c->sr_id > 0) ? (1LL << (c->sr_id - 1)) : 0LL;
    }
    c->scale = scale;
}

// Bit-exact integer multiply-shift-round (round half away from zero)
__device__ __forceinline__ long long fpmul(int xi, int nm, int sr, int sl,
                                           int left, long long k) {
    long long tmp = (long long)xi * (long long)nm;   // IMAD.WIDE
    if (left) return tmp << sl;
    if (sr == 0) return tmp;
    return (tmp + (k - (long long)(tmp < 0))) >> sr; // arithmetic shift
}

__device__ __forceinline__ float quant_one(float xv, float iv, const Consts& c) {
    int xi = (int)xv;        // exact: inputs are integer-valued fp32
    int ii = (int)iv;
    long long rx = fpmul(xi, c.nm_x,  c.sr_x,  c.sl_x,  c.left_x,  c.kx);
    long long ri = fpmul(ii, c.nm_id, c.sr_id, c.sl_id, c.left_id, c.kid);
    long long s  = rx + ri;
    int q = (int)(s < -128 ? -128 : (s > 127 ? 127 : s));
    return (float)q * c.scale;
}

__device__ __forceinline__ float4 quant4(float4 xv, float4 iv, const Consts& c) {
    float4 ov;
    ov.x = quant_one(xv.x, iv.x, c);
    ov.y = quant_one(xv.y, iv.y, c);
    ov.z = quant_one(xv.z, iv.z, c);
    ov.w = quant_one(xv.w, iv.w, c);
    return ov;
}

__global__ void __launch_bounds__(256)
fused_quant_kernel(const float4* __restrict__ x,
                   const float4* __restrict__ idn,
                   float4* __restrict__ out,
                   const float* __restrict__ pre_sf,
                   const float* __restrict__ id_sf,
                   const float* __restrict__ x_min,
                   const float* __restrict__ x_max,
                   int n4, int n, int out_size) {
    __shared__ Consts sc;
    if (threadIdx.x == 0) {
        compute_consts(pre_sf, id_sf, x_min, x_max, &sc);
    }
    __syncthreads();
    const Consts c = sc;

    const int bdim    = blockDim.x;                  // 256
    const int stride2 = gridDim.x * bdim * 2;        // elements (float4) per sweep

    // Persistent grid-stride, 2x float4 per thread per iteration.
    // All 4 loads are issued before any compute (MLP_p1 = 4).
    for (int i = blockIdx.x * bdim * 2 + threadIdx.x; i < n4; i += stride2) {
        int j = i + bdim;
        bool has2 = (j < n4);

        float4 x0 = __ldcs(&x[i]);
        float4 i0 = __ldcs(&idn[i]);
        float4 x1, i1;
        if (has2) {
            x1 = __ldcs(&x[j]);
            i1 = __ldcs(&idn[j]);
        }

        __stcs(&out[i], quant4(x0, i0, c));
        if (has2) {
            __stcs(&out[j], quant4(x1, i1, c));
        }
    }

    // Block 0 handles: scalar remainder (n % 4) and extra output elements
    // (the reference also returns `scale` — harness may flatten it after act).
    if (blockIdx.x == 0) {
        int rem_start = n4 << 2;
        const float* xs = (const float*)x;
        const float* is = (const float*)idn;
        float*       os = (float*)out;
        for (int i = rem_start + threadIdx.x; i < n; i += bdim) {
            os[i] = quant_one(xs[i], is[i], c);
        }
        for (int i = n + threadIdx.x; i < out_size; i += bdim) {
            os[i] = c.scale;
        }
    }
}

extern "C" void kernel_launch(void* const* d_in, const int* in_sizes, int n_in,
                              void* d_out, int out_size) {
    const float* x      = (const float*)d_in[0];
    const float* idn    = (const float*)d_in[1];
    const float* pre_sf = (const float*)d_in[2];
    const float* id_sf  = (const float*)d_in[3];
    const float* x_min  = (const float*)d_in[4];
    const float* x_max  = (const float*)d_in[5];
    float* out = (float*)d_out;

    int n  = in_sizes[0];
    int n4 = n >> 2;

    const int threads = 256;
    // Persistent-ish grid: enough blocks to fill the chip several times over,
    // capped so the per-block const computation stays amortized.
    long long needed = ((long long)n4 + threads * 2 - 1) / (threads * 2);
    int blocks = (int)(needed < 1 ? 1 : (needed > 2368 ? 2368 : needed));

    fused_quant_kernel<<<blocks, threads>>>(
        (const float4*)x, (const float4*)idn, (float4*)out,
        pre_sf, id_sf, x_min, x_max, n4, n, out_size);
}

// round 11
// speedup vs baseline: 1.3090x; 1.0459x over previous
#include <cuda_runtime.h>

#define ACC 23

struct Consts {
    int       nm_x, nm_id;
    int       sr_x, sr_id;
    int       sl_x, sl_id;
    int       left_x, left_id;
    int       kx32, kid32;   // (1 << (sr-1)), 0 if sr==0 (fits int32 when sr<=31)
    long long kx, kid;       // 64-bit versions for generic path
    int       fast;          // both streams eligible for 32-bit fast path
    float     scale;
};

// Exact replication of the reference's fp64 scale decomposition.
__device__ __forceinline__ void compute_consts(const float* __restrict__ pre_sf,
                                               const float* __restrict__ id_sf,
                                               const float* __restrict__ x_min,
                                               const float* __restrict__ x_max,
                                               Consts* c) {
    float scale = fmaxf(fabsf(x_min[0]), fabsf(x_max[0]));
    scale = fmaxf(scale, 1e-8f);
    scale = scale / 127.0f;
    double s64 = (double)scale;
    {
        double ns = (double)pre_sf[0] / s64;
        int e; double m = frexp(ns, &e);             // m in [0.5, 1)
        c->nm_x   = (int)llrint(m * 8388608.0);      // round-half-even == jnp.round
        c->sl_x   = max(e - ACC, 0);
        c->sr_x   = max(ACC - e, 0);
        c->left_x = (e - ACC) >= 0;
        c->kx32   = (c->sr_x > 0 && c->sr_x <= 31) ? (1 << (c->sr_x - 1)) : 0;
        c->kx     = (c->sr_x > 0) ? (1LL << (c->sr_x - 1)) : 0LL;
    }
    {
        double ns = (double)id_sf[0] / s64;
        int e; double m = frexp(ns, &e);
        c->nm_id   = (int)llrint(m * 8388608.0);
        c->sl_id   = max(e - ACC, 0);
        c->sr_id   = max(ACC - e, 0);
        c->left_id = (e - ACC) >= 0;
        c->kid32   = (c->sr_id > 0 && c->sr_id <= 31) ? (1 << (c->sr_id - 1)) : 0;
        c->kid     = (c->sr_id > 0) ? (1LL << (c->sr_id - 1)) : 0LL;
    }
    // Fast path: right-shift branch on both streams, sr in [15,31].
    // sr >= 15 guarantees |(xi*nm)>>sr| < 2^31 for |xi| < 2^22 (exact-int fp32
    // inputs from int32 accumulators), so 32-bit extraction is exact.
    c->fast = (!c->left_x && !c->left_id &&
               c->sr_x >= 15 && c->sr_x <= 31 &&
               c->sr_id >= 15 && c->sr_id <= 31);
    c->scale = scale;
}

// ---------------- generic bit-exact path (any consts) ----------------
__device__ __forceinline__ long long fpmul_gen(int xi, int nm, int sr, int sl,
                                               int left, long long k) {
    long long tmp = (long long)xi * (long long)nm;
    if (left) return tmp << sl;
    if (sr == 0) return tmp;
    return (tmp + (k - (long long)(tmp < 0))) >> sr;
}

__device__ __forceinline__ float quant_gen(float xv, float iv, const Consts& c) {
    int xi = (int)xv;
    int ii = (int)iv;
    long long rx = fpmul_gen(xi, c.nm_x,  c.sr_x,  c.sl_x,  c.left_x,  c.kx);
    long long ri = fpmul_gen(ii, c.nm_id, c.sr_id, c.sl_id, c.left_id, c.kid);
    long long s  = rx + ri;
    int q = (int)(s < -128 ? -128 : (s > 127 ? 127 : s));
    return (float)q * c.scale;
}

// ---------------- fast 32-bit path ----------------
// float -> int, exact for integer-valued v with |v| < 2^22
__device__ __forceinline__ int f2i_magic(float v) {
    float f = v + 12582912.0f;             // 2^23 + 2^22
    return __float_as_int(f) - 0x4B400000;
}
// int -> float, exact for q in [-2^22, 2^22)
__device__ __forceinline__ float i2f_magic(int q) {
    return __int_as_float(q + 0x4B400000) - 12582912.0f;
}

// round((xi*nm) / 2^sr) half-away-from-zero; nm > 0 so sign(tmp) == sign(xi).
__device__ __forceinline__ int fpmul_fast(int xi, int nm, int sr, int k) {
    unsigned b = (unsigned)xi >> 31;                       // 1 = negative
    long long tmp = (long long)xi * (long long)nm
                  + (long long)(unsigned)(k - (int)b);     // IMAD.WIDE w/ addend
    unsigned lo = (unsigned)tmp;
    unsigned hi = (unsigned)((unsigned long long)tmp >> 32);
    return (int)__funnelshift_r(lo, hi, sr);               // low 32 bits of >> sr
}

__device__ __forceinline__ float quant_fast(float xv, float iv, const Consts& c) {
    int xi = f2i_magic(xv);
    int ii = f2i_magic(iv);
    int rx = fpmul_fast(xi, c.nm_x,  c.sr_x,  c.kx32);
    int ri = fpmul_fast(ii, c.nm_id, c.sr_id, c.kid32);
    int s  = rx + ri;
    s = max(s, -128);
    s = min(s, 127);
    return i2f_magic(s) * c.scale;
}

__device__ __forceinline__ float4 quant4_fast(float4 xv, float4 iv, const Consts& c) {
    float4 ov;
    ov.x = quant_fast(xv.x, iv.x, c);
    ov.y = quant_fast(xv.y, iv.y, c);
    ov.z = quant_fast(xv.z, iv.z, c);
    ov.w = quant_fast(xv.w, iv.w, c);
    return ov;
}

__device__ __forceinline__ float4 quant4_gen(float4 xv, float4 iv, const Consts& c) {
    float4 ov;
    ov.x = quant_gen(xv.x, iv.x, c);
    ov.y = quant_gen(xv.y, iv.y, c);
    ov.z = quant_gen(xv.z, iv.z, c);
    ov.w = quant_gen(xv.w, iv.w, c);
    return ov;
}

__global__ void __launch_bounds__(256)
fused_quant_kernel(const float4* __restrict__ x,
                   const float4* __restrict__ idn,
                   float4* __restrict__ out,
                   const float* __restrict__ pre_sf,
                   const float* __restrict__ id_sf,
                   const float* __restrict__ x_min,
                   const float* __restrict__ x_max,
                   int n4, int n, int out_size) {
    __shared__ Consts sc;
    if (threadIdx.x == 0) {
        compute_consts(pre_sf, id_sf, x_min, x_max, &sc);
    }
    __syncthreads();
    const Consts c = sc;

    const int bdim    = blockDim.x;                  // 256
    const int stride2 = gridDim.x * bdim * 2;        // float4 elements per sweep

    if (c.fast) {
        for (int i = blockIdx.x * bdim * 2 + threadIdx.x; i < n4; i += stride2) {
            int j = i + bdim;
            bool has2 = (j < n4);

            float4 x0 = __ldcs(&x[i]);
            float4 i0 = __ldcs(&idn[i]);
            float4 x1, i1;
            if (has2) {
                x1 = __ldcs(&x[j]);
                i1 = __ldcs(&idn[j]);
            }

            __stcs(&out[i], quant4_fast(x0, i0, c));
            if (has2) {
                __stcs(&out[j], quant4_fast(x1, i1, c));
            }
        }
    } else {
        for (int i = blockIdx.x * bdim * 2 + threadIdx.x; i < n4; i += stride2) {
            int j = i + bdim;
            bool has2 = (j < n4);

            float4 x0 = __ldcs(&x[i]);
            float4 i0 = __ldcs(&idn[i]);
            float4 x1, i1;
            if (has2) {
                x1 = __ldcs(&x[j]);
                i1 = __ldcs(&idn[j]);
            }

            __stcs(&out[i], quant4_gen(x0, i0, c));
            if (has2) {
                __stcs(&out[j], quant4_gen(x1, i1, c));
            }
        }
    }

    // Block 0: scalar remainder (n % 4) and any extra output elements
    // (the reference also returns `scale`).
    if (blockIdx.x == 0) {
        int rem_start = n4 << 2;
        const float* xs = (const float*)x;
        const float* is = (const float*)idn;
        float*       os = (float*)out;
        for (int i = rem_start + threadIdx.x; i < n; i += bdim) {
            os[i] = quant_gen(xs[i], is[i], c);
        }
        for (int i = n + threadIdx.x; i < out_size; i += bdim) {
            os[i] = c.scale;
        }
    }
}

extern "C" void kernel_launch(void* const* d_in, const int* in_sizes, int n_in,
                              void* d_out, int out_size) {
    const float* x      = (const float*)d_in[0];
    const float* idn    = (const float*)d_in[1];
    const float* pre_sf = (const float*)d_in[2];
    const float* id_sf  = (const float*)d_in[3];
    const float* x_min  = (const float*)d_in[4];
    const float* x_max  = (const float*)d_in[5];
    float* out = (float*)d_out;

    int n  = in_sizes[0];
    int n4 = n >> 2;

    const int threads = 256;
    long long needed = ((long long)n4 + threads * 2 - 1) / (threads * 2);
    int blocks = (int)(needed < 1 ? 1 : (needed > 2368 ? 2368 : needed));

    fused_quant_kernel<<<blocks, threads>>>(
        (const float4*)x, (const float4*)idn, (float4*)out,
        pre_sf, id_sf, x_min, x_max, n4, n, out_size);
}

// round 12
// speedup vs baseline: 1.3441x; 1.0268x over previous
#include <cuda_runtime.h>

#define ACC 23

struct Consts {
    int       nm_x, nm_id;
    int       sr_x, sr_id;
    int       sl_x, sl_id;
    int       left_x, left_id;
    int       kx32, kid32;   // (1 << (sr-1)), 0 if sr==0 (fits int32 when sr<=31)
    long long kx, kid;       // 64-bit versions for generic path
    int       fast;          // both streams eligible for 32-bit fast path
    float     scale;
};

// Exact replication of the reference's fp64 scale decomposition.
__device__ __forceinline__ void compute_consts(const float* __restrict__ pre_sf,
                                               const float* __restrict__ id_sf,
                                               const float* __restrict__ x_min,
                                               const float* __restrict__ x_max,
                                               Consts* c) {
    float scale = fmaxf(fabsf(x_min[0]), fabsf(x_max[0]));
    scale = fmaxf(scale, 1e-8f);
    scale = scale / 127.0f;
    double s64 = (double)scale;
    {
        double ns = (double)pre_sf[0] / s64;
        int e; double m = frexp(ns, &e);             // m in [0.5, 1)
        c->nm_x   = (int)llrint(m * 8388608.0);      // round-half-even == jnp.round
        c->sl_x   = max(e - ACC, 0);
        c->sr_x   = max(ACC - e, 0);
        c->left_x = (e - ACC) >= 0;
        c->kx32   = (c->sr_x > 0 && c->sr_x <= 31) ? (1 << (c->sr_x - 1)) : 0;
        c->kx     = (c->sr_x > 0) ? (1LL << (c->sr_x - 1)) : 0LL;
    }
    {
        double ns = (double)id_sf[0] / s64;
        int e; double m = frexp(ns, &e);
        c->nm_id   = (int)llrint(m * 8388608.0);
        c->sl_id   = max(e - ACC, 0);
        c->sr_id   = max(ACC - e, 0);
        c->left_id = (e - ACC) >= 0;
        c->kid32   = (c->sr_id > 0 && c->sr_id <= 31) ? (1 << (c->sr_id - 1)) : 0;
        c->kid     = (c->sr_id > 0) ? (1LL << (c->sr_id - 1)) : 0LL;
    }
    // Fast path: right-shift branch on both streams, sr in [15,31].
    // sr >= 15 guarantees |(xi*nm)>>sr| < 2^31 for |xi| < 2^22 (exact-int fp32
    // inputs from int32 accumulators), so 32-bit extraction is exact.
    c->fast = (!c->left_x && !c->left_id &&
               c->sr_x >= 15 && c->sr_x <= 31 &&
               c->sr_id >= 15 && c->sr_id <= 31);
    c->scale = scale;
}

// ---------------- generic bit-exact path (any consts) ----------------
__device__ __forceinline__ long long fpmul_gen(int xi, int nm, int sr, int sl,
                                               int left, long long k) {
    long long tmp = (long long)xi * (long long)nm;
    if (left) return tmp << sl;
    if (sr == 0) return tmp;
    return (tmp + (k - (long long)(tmp < 0))) >> sr;
}

__device__ __forceinline__ float quant_gen(float xv, float iv, const Consts& c) {
    int xi = (int)xv;
    int ii = (int)iv;
    long long rx = fpmul_gen(xi, c.nm_x,  c.sr_x,  c.sl_x,  c.left_x,  c.kx);
    long long ri = fpmul_gen(ii, c.nm_id, c.sr_id, c.sl_id, c.left_id, c.kid);
    long long s  = rx + ri;
    int q = (int)(s < -128 ? -128 : (s > 127 ? 127 : s));
    return (float)q * c.scale;
}

// ---------------- fast 32-bit path ----------------
// float -> int, exact for integer-valued v with |v| < 2^22
__device__ __forceinline__ int f2i_magic(float v) {
    float f = v + 12582912.0f;             // 2^23 + 2^22
    return __float_as_int(f) - 0x4B400000;
}
// int -> float, exact for q in [-2^22, 2^22)
__device__ __forceinline__ float i2f_magic(int q) {
    return __int_as_float(q + 0x4B400000) - 12582912.0f;
}

// round((xi*nm) / 2^sr) half-away-from-zero; nm > 0 so sign(tmp) == sign(xi).
__device__ __forceinline__ int fpmul_fast(int xi, int nm, int sr, int k) {
    unsigned b = (unsigned)xi >> 31;                       // 1 = negative
    long long tmp = (long long)xi * (long long)nm
                  + (long long)(unsigned)(k - (int)b);     // IMAD.WIDE w/ addend
    unsigned lo = (unsigned)tmp;
    unsigned hi = (unsigned)((unsigned long long)tmp >> 32);
    return (int)__funnelshift_r(lo, hi, sr);               // low 32 bits of >> sr
}

__device__ __forceinline__ float quant_fast(float xv, float iv, const Consts& c) {
    int xi = f2i_magic(xv);
    int ii = f2i_magic(iv);
    int rx = fpmul_fast(xi, c.nm_x,  c.sr_x,  c.kx32);
    int ri = fpmul_fast(ii, c.nm_id, c.sr_id, c.kid32);
    int s  = rx + ri;
    s = max(s, -128);
    s = min(s, 127);
    return i2f_magic(s) * c.scale;
}

__device__ __forceinline__ float4 quant4_fast(float4 xv, float4 iv, const Consts& c) {
    float4 ov;
    ov.x = quant_fast(xv.x, iv.x, c);
    ov.y = quant_fast(xv.y, iv.y, c);
    ov.z = quant_fast(xv.z, iv.z, c);
    ov.w = quant_fast(xv.w, iv.w, c);
    return ov;
}

__device__ __forceinline__ float4 quant4_gen(float4 xv, float4 iv, const Consts& c) {
    float4 ov;
    ov.x = quant_gen(xv.x, iv.x, c);
    ov.y = quant_gen(xv.y, iv.y, c);
    ov.z = quant_gen(xv.z, iv.z, c);
    ov.w = quant_gen(xv.w, iv.w, c);
    return ov;
}

#define UNROLL 4

__global__ void __launch_bounds__(256)
fused_quant_kernel(const float4* __restrict__ x,
                   const float4* __restrict__ idn,
                   float4* __restrict__ out,
                   const float* __restrict__ pre_sf,
                   const float* __restrict__ id_sf,
                   const float* __restrict__ x_min,
                   const float* __restrict__ x_max,
                   int n4, int n, int out_size) {
    __shared__ Consts sc;
    if (threadIdx.x == 0) {
        compute_consts(pre_sf, id_sf, x_min, x_max, &sc);
    }
    __syncthreads();
    const Consts c = sc;

    const int bdim   = blockDim.x;                       // 256
    const int stride = gridDim.x * bdim * UNROLL;        // float4 per sweep

    if (c.fast) {
        for (int i = blockIdx.x * bdim * UNROLL + threadIdx.x; i < n4; i += stride) {
            float4 xv[UNROLL], iv[UNROLL];
            bool   ok[UNROLL];
            // Batch all loads up front (deep L1tex queue fill)
            #pragma unroll
            for (int u = 0; u < UNROLL; u++) {
                int idx = i + u * bdim;
                ok[u] = (idx < n4);
                if (ok[u]) {
                    xv[u] = __ldcs(&x[idx]);
                    iv[u] = __ldcs(&idn[idx]);
                }
            }
            #pragma unroll
            for (int u = 0; u < UNROLL; u++) {
                if (ok[u]) {
                    __stcs(&out[i + u * bdim], quant4_fast(xv[u], iv[u], c));
                }
            }
        }
    } else {
        for (int i = blockIdx.x * bdim * UNROLL + threadIdx.x; i < n4; i += stride) {
            float4 xv[UNROLL], iv[UNROLL];
            bool   ok[UNROLL];
            #pragma unroll
            for (int u = 0; u < UNROLL; u++) {
                int idx = i + u * bdim;
                ok[u] = (idx < n4);
                if (ok[u]) {
                    xv[u] = __ldcs(&x[idx]);
                    iv[u] = __ldcs(&idn[idx]);
                }
            }
            #pragma unroll
            for (int u = 0; u < UNROLL; u++) {
                if (ok[u]) {
                    __stcs(&out[i + u * bdim], quant4_gen(xv[u], iv[u], c));
                }
            }
        }
    }

    // Block 0: scalar remainder (n % 4) and any extra output elements
    // (the reference also returns `scale`).
    if (blockIdx.x == 0) {
        int rem_start = n4 << 2;
        const float* xs = (const float*)x;
        const float* is = (const float*)idn;
        float*       os = (float*)out;
        for (int i = rem_start + threadIdx.x; i < n; i += bdim) {
            os[i] = quant_gen(xs[i], is[i], c);
        }
        for (int i = n + threadIdx.x; i < out_size; i += bdim) {
            os[i] = c.scale;
        }
    }
}

extern "C" void kernel_launch(void* const* d_in, const int* in_sizes, int n_in,
                              void* d_out, int out_size) {
    const float* x      = (const float*)d_in[0];
    const float* idn    = (const float*)d_in[1];
    const float* pre_sf = (const float*)d_in[2];
    const float* id_sf  = (const float*)d_in[3];
    const float* x_min  = (const float*)d_in[4];
    const float* x_max  = (const float*)d_in[5];
    float* out = (float*)d_out;

    int n  = in_sizes[0];
    int n4 = n >> 2;

    const int threads = 256;
    long long needed = ((long long)n4 + threads * UNROLL - 1) / (threads * UNROLL);
    int blocks = (int)(needed < 1 ? 1 : (needed > 2368 ? 2368 : needed));

    fused_quant_kernel<<<blocks, threads>>>(
        (const float4*)x, (const float4*)idn, (float4*)out,
        pre_sf, id_sf, x_min, x_max, n4, n, out_size);
}